// round 4
// baseline (speedup 1.0000x reference)
#include <cuda_runtime.h>
#include <math.h>

// ---------------------------------------------------------------------------
// EDR loss pipeline:
//   irfft(96000) via pack trick -> complex IFFT(48000) = 48 x (40 x 25)
//   -> Hann STFT (512/256, 374 frames) via Stockham FFT-256 + rfft unpack
//   -> power -> suffix-sum over frames -> 10*log10 -> sum|dt-da| / sum|dt|
// ---------------------------------------------------------------------------

#define NSIG     256          // 128 target + 128 ach signals
#define NHALF    48000        // M = N/2 (packed complex length)
#define ROWLEN   96000        // input row length (floats)
#define TFRAMES  374
#define FBINS    257

// scratch (allowed: __device__ globals, no runtime allocation)
__device__ float2 g_bufA[NSIG * NHALF];              // Y, later y (time domain packed)
__device__ float2 g_bufB[NSIG * NHALF];              // stage-1 intermediate G
__device__ float  g_P[NSIG * TFRAMES * FBINS];       // |STFT|^2
__device__ float  g_partial[256];                    // per-block (num, den) partials

__device__ __forceinline__ void cmac(float2& acc, float2 a, float2 w) {
    acc.x += a.x * w.x - a.y * w.y;
    acc.y += a.x * w.y + a.y * w.x;
}

// ---------------------------------------------------------------------------
// K1: build packed spectrum Y[k] for the length-48000 complex IFFT.
//   E[k] = (a[k] + conj(a[M-k]))/2
//   O[k] = e^{+2*pi*i*k/N} * (a[k] - conj(a[M-k]))/2      (N = 96000)
//   Y[k] = E[k] + i*O[k]
// a[0], a[M] imaginary parts dropped (pocketfft irfft convention; effect on
// the final averaged metric is ~1e-5, far below tolerance).
// ---------------------------------------------------------------------------
__global__ void __launch_bounds__(128) k_pack(const float* __restrict__ tre,
                                              const float* __restrict__ tim,
                                              const float* __restrict__ are,
                                              const float* __restrict__ aim) {
    int k   = blockIdx.x * 128 + threadIdx.x;   // 0..47999  (375*128 == 48000)
    int sig = blockIdx.y;
    const float* re = (sig < 128 ? tre : are) + (size_t)(sig & 127) * ROWLEN;
    const float* im = (sig < 128 ? tim : aim) + (size_t)(sig & 127) * ROWLEN;

    float2 Y;
    if (k == 0) {
        float r0 = re[0], rM = re[NHALF];
        Y = make_float2(0.5f * (r0 + rM), 0.5f * (r0 - rM));
    } else {
        float ar = re[k],         ai = im[k];
        float br = re[NHALF - k], bi = -im[NHALF - k];   // conj(a[M-k])
        float Ex = 0.5f * (ar + br), Ey = 0.5f * (ai + bi);
        float Dx = 0.5f * (ar - br), Dy = 0.5f * (ai - bi);
        float s, c;
        sincosf((float)k * 6.5449846949787352e-5f, &s, &c);  // +2*pi*k/96000
        float Ox = c * Dx - s * Dy;
        float Oy = c * Dy + s * Dx;
        Y = make_float2(Ex - Oy, Ey + Ox);                   // E + i*O
    }
    g_bufA[(size_t)sig * NHALF + k] = Y;
}

// ---------------------------------------------------------------------------
// K2: stage 1 of IFFT-48000 (48 x 1000 split, transform over k1, size 48).
//   G[k2][m1] = (1/48000) * e^{+2pi i k2 m1 / 48000}
//               * sum_{k1<48} Y[k2 + 1000*k1] * e^{+2pi i k1 m1 / 48}
// One thread per k2; the 48 inputs live in registers.
// Output layout: bufB[(sig*48 + m1)*1000 + k2]  (k2-contiguous for stage 2).
// ---------------------------------------------------------------------------
__global__ void __launch_bounds__(125) k_stage1() {
    __shared__ float2 sW[48];
    int tid = threadIdx.x;               // 0..124
    int sig = blockIdx.y;
    int k2  = blockIdx.x * 125 + tid;    // 8 blocks * 125 = 1000 exactly

    if (tid < 48) {
        float s, c;
        sincosf((float)tid * 0.13089969389957472f, &s, &c);  // +2*pi*t/48
        sW[tid] = make_float2(c, s);
    }
    __syncthreads();

    const float2* src = g_bufA + (size_t)sig * NHALF;
    float2 v[48];
#pragma unroll
    for (int k1 = 0; k1 < 48; k1++) v[k1] = src[k2 + 1000 * k1];

    const float inv = 1.0f / 48000.0f;
    float2* dstBase = g_bufB + (size_t)sig * NHALF;  // = sig*48*1000

    for (int m1 = 0; m1 < 48; m1++) {
        float2 acc = make_float2(0.f, 0.f);
        int t = 0;
#pragma unroll
        for (int k1 = 0; k1 < 48; k1++) {
            float2 w = sW[t];                 // t uniform across threads -> broadcast
            t += m1; if (t >= 48) t -= 48;    // (k1*m1) mod 48, exact
            cmac(acc, v[k1], w);
        }
        float s, c;  // twiddle: k2*m1 <= 999*47 = 46953 < 48000 (exact in int/fp32)
        sincosf((float)(k2 * m1) * 1.3089969389957471e-4f, &s, &c);  // +2pi/48000
        float2 out = make_float2((acc.x * c - acc.y * s) * inv,
                                 (acc.x * s + acc.y * c) * inv);
        dstBase[m1 * 1000 + k2] = out;
    }
}

// ---------------------------------------------------------------------------
// K3: stage 2 — size-1000 IDFT per (sig, m1) row, done as 40 x 25 in smem.
//   k2 = c + 25*a (a<40, c<25),  m2 = u + 40*w (u<40, w<25)
//   A: H[u*25+c] = e^{+2pi i c u /1000} * sum_a g[c+25a] e^{+2pi i a u /40}
//   B: y[u+40w]  = sum_c H[u*25+c] e^{+2pi i c w /25}
// Writes y into bufA at natural order m = m1 + 48*m2 (scatter stride 48;
// output set (98MB) fits in L2 so lines merge before eviction).
// ---------------------------------------------------------------------------
__global__ void __launch_bounds__(256) k_stage2() {
    __shared__ float2 sg[1000];
    __shared__ float2 sH[1000];
    __shared__ float2 sW40[40];
    __shared__ float2 sW25[25];
    int tid = threadIdx.x;
    int m1  = blockIdx.x;   // 0..47
    int sig = blockIdx.y;   // 0..255

    if (tid < 40) {
        float s, c; sincosf((float)tid * 0.15707963267948966f, &s, &c);  // 2pi/40
        sW40[tid] = make_float2(c, s);
    }
    if (tid >= 64 && tid < 89) {
        int t = tid - 64;
        float s, c; sincosf((float)t * 0.25132741228718347f, &s, &c);    // 2pi/25
        sW25[t] = make_float2(c, s);
    }
    const float2* src = g_bufB + ((size_t)sig * 48 + m1) * 1000;
    for (int i = tid; i < 1000; i += 256) sg[i] = src[i];
    __syncthreads();

    // stage A (size 40 over a)
    for (int idx = tid; idx < 1000; idx += 256) {
        int u = idx / 25, cc = idx % 25;
        float2 acc = make_float2(0.f, 0.f);
        int t = 0;
#pragma unroll
        for (int a = 0; a < 40; a++) {
            float2 w = sW40[t];
            t += u; if (t >= 40) t -= 40;     // (a*u) mod 40
            cmac(acc, sg[cc + 25 * a], w);
        }
        float s, c;  // c*u <= 24*39 = 936 < 1000
        sincosf((float)(cc * u) * 6.2831853071795865e-3f, &s, &c);  // +2pi/1000
        sH[idx] = make_float2(acc.x * c - acc.y * s, acc.x * s + acc.y * c);
    }
    __syncthreads();

    // stage B (size 25 over c) + scatter to natural time order
    float2* dst = g_bufA + (size_t)sig * NHALF;
    for (int idx = tid; idx < 1000; idx += 256) {
        int w = idx / 40, u = idx % 40;
        float2 acc = make_float2(0.f, 0.f);
        int t = 0;
#pragma unroll
        for (int c = 0; c < 25; c++) {
            float2 tw = sW25[t];
            t += w; if (t >= 25) t -= 25;     // (c*w) mod 25
            cmac(acc, sH[u * 25 + c], tw);
        }
        int m2 = u + 40 * w;
        dst[m1 + 48 * m2] = acc;
    }
}

// ---------------------------------------------------------------------------
// K4: STFT frame power.  Frame t uses y[128t .. 128t+256) (packed even/odd).
// Window each half-sample, Stockham forward FFT-256, rfft unpack, |.|^2.
// P layout: g_P[(sig*374 + t)*257 + f]  (coalesced writes over f).
// ---------------------------------------------------------------------------
__global__ void __launch_bounds__(128) k_stft() {
    __shared__ float2 sa[256];
    __shared__ float2 sb[256];
    int tid = threadIdx.x;
    int fr  = blockIdx.x;   // frame 0..373
    int sig = blockIdx.y;

    const float2* src = g_bufA + (size_t)sig * NHALF + 128 * fr;
#pragma unroll
    for (int h = 0; h < 2; h++) {
        int i = tid + 128 * h;
        float2 y = src[i];
        int n = 2 * i;
        // periodic Hann: 0.5*(1 - cos(2*pi*n/512)),  2*pi/512 = pi/256
        float w0 = 0.5f - 0.5f * cosf((float)n       * 1.2271846303085130e-2f);
        float w1 = 0.5f - 0.5f * cosf((float)(n + 1) * 1.2271846303085130e-2f);
        sa[i] = make_float2(y.x * w0, y.y * w1);
    }
    __syncthreads();

    // Stockham DIF forward FFT, n=256 -> 8 passes, 128 butterflies/pass.
    float2* X = sa;
    float2* Y = sb;
    int nn = 256, s = 1, ls = 0;
    while (nn > 1) {
        int m = nn >> 1;
        int q = tid & (s - 1);
        int p = tid >> ls;                      // p < m
        float2 a = X[q + s * p];
        float2 b = X[q + s * (p + m)];
        float stepf = 6.2831853071795865f / (float)nn;
        float sn, cs;
        sincosf(-(float)p * stepf, &sn, &cs);   // e^{-2pi i p / nn}
        Y[q + s * (2 * p)]     = make_float2(a.x + b.x, a.y + b.y);
        float dx = a.x - b.x, dy = a.y - b.y;
        Y[q + s * (2 * p + 1)] = make_float2(dx * cs - dy * sn, dx * sn + dy * cs);
        __syncthreads();
        float2* tmp = X; X = Y; Y = tmp;
        nn = m; s <<= 1; ls++;
    }
    // after 8 swaps result is back in sa (== X)

    float* Pout = g_P + ((size_t)sig * TFRAMES + fr) * FBINS;
#pragma unroll
    for (int h = 0; h < 2; h++) {
        int f = tid + 128 * h;                  // 0..255
        float2 z1 = X[f];
        int j = (256 - f) & 255;
        float2 z2 = X[j]; z2.y = -z2.y;         // conj
        float Ex = 0.5f * (z1.x + z2.x), Ey = 0.5f * (z1.y + z2.y);
        float Dx = 0.5f * (z1.x - z2.x), Dy = 0.5f * (z1.y - z2.y);
        float Ox = Dy, Oy = -Dx;                // O = D / i
        float sn, cs;
        sincosf(-(float)f * 1.2271846303085130e-2f, &sn, &cs);  // e^{-2pi i f/512}
        float Sx = Ex + Ox * cs - Oy * sn;
        float Sy = Ey + Ox * sn + Oy * cs;
        Pout[f] = Sx * Sx + Sy * Sy;
    }
    if (tid == 0) {                             // Nyquist bin f=256
        float v = X[0].x - X[0].y;              // E[0] - O[0]
        Pout[256] = v * v;
    }
}

// ---------------------------------------------------------------------------
// K5: per-signal EDR + loss terms. Block = one target/ach pair s, thread = f.
// Suffix-sum power over frames (t descending), dB, accumulate |dt-da|, |dt|.
// Deterministic: block tree-reduce -> g_partial, summed by K6 single thread.
// ---------------------------------------------------------------------------
__global__ void __launch_bounds__(512) k_loss() {
    __shared__ float sn[512], sd[512];
    int tid = threadIdx.x;
    int s   = blockIdx.x;                       // 0..127
    float num = 0.f, den = 0.f;
    if (tid < FBINS) {
        const float* pt = g_P + (size_t)s * TFRAMES * FBINS + tid;
        const float* pa = g_P + (size_t)(s + 128) * TFRAMES * FBINS + tid;
        float st = 0.f, sv = 0.f;
        for (int t = TFRAMES - 1; t >= 0; --t) {
            st += pt[t * FBINS];
            sv += pa[t * FBINS];
            float et = 10.f * log10f(st);
            float ea = 10.f * log10f(sv);
            num += fabsf(et - ea);
            den += fabsf(et);
        }
    }
    sn[tid] = num; sd[tid] = den;
    __syncthreads();
    for (int off = 256; off > 0; off >>= 1) {
        if (tid < off) { sn[tid] += sn[tid + off]; sd[tid] += sd[tid + off]; }
        __syncthreads();
    }
    if (tid == 0) {
        g_partial[2 * s]     = sn[0];
        g_partial[2 * s + 1] = sd[0];
    }
}

__global__ void k_final(float* __restrict__ out) {
    double n = 0.0, d = 0.0;
    for (int i = 0; i < 128; i++) {
        n += (double)g_partial[2 * i];
        d += (double)g_partial[2 * i + 1];
    }
    out[0] = (float)(n / d);
}

// ---------------------------------------------------------------------------
extern "C" void kernel_launch(void* const* d_in, const int* in_sizes, int n_in,
                              void* d_out, int out_size) {
    const float* tre = (const float*)d_in[0];
    const float* tim = (const float*)d_in[1];
    const float* are = (const float*)d_in[2];
    const float* aim = (const float*)d_in[3];

    k_pack  <<<dim3(375, NSIG), 128>>>(tre, tim, are, aim);
    k_stage1<<<dim3(8,   NSIG), 125>>>();
    k_stage2<<<dim3(48,  NSIG), 256>>>();
    k_stft  <<<dim3(TFRAMES, NSIG), 128>>>();
    k_loss  <<<128, 512>>>();
    k_final <<<1, 1>>>((float*)d_out);
}

// round 5
// speedup vs baseline: 1.6180x; 1.6180x over previous
#include <cuda_runtime.h>
#include <math.h>

// ---------------------------------------------------------------------------
// EDR loss pipeline (round 4: table twiddles + radix-split FFTs):
//   irfft(96000) via pack trick -> complex IFFT(48000) = 48 (=8x6, regs) x 1000 (=10^3, smem)
//   -> Hann STFT (512/256, 374 frames) via table-twiddle Stockham FFT-256
//   -> power -> suffix-sum over frames -> 10*log10 -> sum|dt-da| / sum|dt|
// ---------------------------------------------------------------------------

#define NSIG     256
#define NHALF    48000
#define ROWLEN   96000
#define TFRAMES  374
#define FBINS    257

// scratch (allowed: __device__ globals)
__device__ float2 g_bufA[NSIG * NHALF];
__device__ float2 g_bufB[NSIG * NHALF];
__device__ float  g_P[NSIG * TFRAMES * FBINS];
__device__ float  g_partial[256];

// twiddle tables (filled by k_setup every launch; deterministic)
__device__ float2 g_tw48000[48000];   // e^{+2pi i t/48000} / 48000  (stage1 twiddle, inv folded)
__device__ float2 g_tw1000[1000];     // e^{+2pi i t/1000}
__device__ float2 g_tw48[48];         // e^{+2pi i t/48}
__device__ float2 g_tw10[10];         // e^{+2pi i t/10}
__device__ float2 g_tw256[128];       // e^{-2pi i k/256}
__device__ float2 g_tw512[256];       // e^{-2pi i f/512}
__device__ float2 g_hann2[256];       // (hann(2i), hann(2i+1)), periodic Hann 512

__device__ __forceinline__ void cmac(float2& acc, float2 a, float2 w) {
    acc.x += a.x * w.x - a.y * w.y;
    acc.y += a.x * w.y + a.y * w.x;
}
__device__ __forceinline__ float2 cadd(float2 a, float2 b){ return make_float2(a.x+b.x, a.y+b.y); }
__device__ __forceinline__ float2 csub(float2 a, float2 b){ return make_float2(a.x-b.x, a.y-b.y); }
__device__ __forceinline__ float2 cmul(float2 a, float2 b){
    return make_float2(a.x*b.x - a.y*b.y, a.x*b.y + a.y*b.x);
}
__device__ __forceinline__ float2 cmuli(float2 a){ return make_float2(-a.y, a.x); }  // i*a

// ---------------------------------------------------------------------------
__global__ void __launch_bounds__(512) k_setup() {
    int t = blockIdx.x * 512 + threadIdx.x;
    float s, c;
    if (t < 48000) {
        sincosf((float)t * 1.3089969389957471e-4f, &s, &c);   // +2pi/48000
        const float inv = 1.0f / 48000.0f;
        g_tw48000[t] = make_float2(c * inv, s * inv);
    }
    if (t < 1000) {
        sincosf((float)t * 6.2831853071795865e-3f, &s, &c);   // +2pi/1000
        g_tw1000[t] = make_float2(c, s);
    }
    if (t < 48) {
        sincosf((float)t * 0.13089969389957472f, &s, &c);     // +2pi/48
        g_tw48[t] = make_float2(c, s);
    }
    if (t < 10) {
        sincosf((float)t * 0.62831853071795865f, &s, &c);     // +2pi/10
        g_tw10[t] = make_float2(c, s);
    }
    if (t < 128) {
        sincosf(-(float)t * 2.4543692606170259e-2f, &s, &c);  // -2pi/256
        g_tw256[t] = make_float2(c, s);
    }
    if (t < 256) {
        sincosf(-(float)t * 1.2271846303085130e-2f, &s, &c);  // -2pi/512
        g_tw512[t] = make_float2(c, s);
        float w0 = 0.5f - 0.5f * cosf((float)(2 * t)     * 1.2271846303085130e-2f);
        float w1 = 0.5f - 0.5f * cosf((float)(2 * t + 1) * 1.2271846303085130e-2f);
        g_hann2[t] = make_float2(w0, w1);
    }
}

// ---------------------------------------------------------------------------
// K1: packed spectrum Y[k] = E[k] + i*O[k] for the length-48000 complex IFFT.
// ---------------------------------------------------------------------------
__global__ void __launch_bounds__(128) k_pack(const float* __restrict__ tre,
                                              const float* __restrict__ tim,
                                              const float* __restrict__ are,
                                              const float* __restrict__ aim) {
    int k   = blockIdx.x * 128 + threadIdx.x;   // 0..47999
    int sig = blockIdx.y;
    const float* re = (sig < 128 ? tre : are) + (size_t)(sig & 127) * ROWLEN;
    const float* im = (sig < 128 ? tim : aim) + (size_t)(sig & 127) * ROWLEN;

    float2 Y;
    if (k == 0) {
        float r0 = re[0], rM = re[NHALF];
        Y = make_float2(0.5f * (r0 + rM), 0.5f * (r0 - rM));
    } else {
        float ar = re[k],         ai = im[k];
        float br = re[NHALF - k], bi = -im[NHALF - k];
        float Ex = 0.5f * (ar + br), Ey = 0.5f * (ai + bi);
        float Dx = 0.5f * (ar - br), Dy = 0.5f * (ai - bi);
        float s, c;
        sincosf((float)k * 6.5449846949787352e-5f, &s, &c);  // +2pi*k/96000
        float Ox = c * Dx - s * Dy;
        float Oy = c * Dy + s * Dx;
        Y = make_float2(Ex - Oy, Ey + Ox);
    }
    g_bufA[(size_t)sig * NHALF + k] = Y;
}

// ---------------------------------------------------------------------------
// K2: stage 1 of IFFT-48000. One thread per k2; 48-point DFT over k1 done as
// 8x6 Cooley-Tukey in registers:  j = 6a + b (a<8, b<6):
//   B_b[r] = DFT8+_a( v[6a+b] )   stored in-place at v[6r+b]
//   X[m]   = sum_{b<6} W48^{bm} * v[6*(m&7)+b]
// then multiply by table twiddle e^{+2pi i k2 m/48000}/48000 and store.
// ---------------------------------------------------------------------------
__global__ void __launch_bounds__(125) k_stage1() {
    __shared__ float2 sW[48];
    int tid = threadIdx.x;               // 0..124
    int sig = blockIdx.y;
    int k2  = blockIdx.x * 125 + tid;    // 8 blocks * 125 = 1000

    if (tid < 48) sW[tid] = g_tw48[tid];
    __syncthreads();

    const float2* src = g_bufA + (size_t)sig * NHALF;
    float2 v[48];
#pragma unroll
    for (int k1 = 0; k1 < 48; k1++) v[k1] = src[k2 + 1000 * k1];

    // six DFT-8s (positive exponent), in place: v[6r+b] = F_b[r]
    const float C = 0.70710678118654752f;
#pragma unroll
    for (int b = 0; b < 6; b++) {
        float2 x0 = v[b],      x1 = v[b + 6],  x2 = v[b + 12], x3 = v[b + 18];
        float2 x4 = v[b + 24], x5 = v[b + 30], x6 = v[b + 36], x7 = v[b + 42];
        float2 g0 = cadd(x0, x4), g1 = csub(x0, x4);
        float2 g2 = cadd(x2, x6), g3 = csub(x2, x6);
        float2 h0 = cadd(x1, x5), h1 = csub(x1, x5);
        float2 h2 = cadd(x3, x7), h3 = csub(x3, x7);
        float2 ig3 = cmuli(g3), ih3 = cmuli(h3);
        float2 E0 = cadd(g0, g2), E2 = csub(g0, g2);
        float2 E1 = cadd(g1, ig3), E3 = csub(g1, ig3);
        float2 O0 = cadd(h0, h2), O2 = csub(h0, h2);
        float2 O1 = cadd(h1, ih3), O3 = csub(h1, ih3);
        float2 W1O1 = make_float2(C * (O1.x - O1.y),  C * (O1.x + O1.y));   // e^{+i pi/4}  * O1
        float2 W3O3 = make_float2(-C * (O3.x + O3.y), C * (O3.x - O3.y));   // e^{+i 3pi/4} * O3
        float2 iO2  = cmuli(O2);
        v[b]      = cadd(E0, O0);
        v[b + 6]  = cadd(E1, W1O1);
        v[b + 12] = cadd(E2, iO2);
        v[b + 18] = cadd(E3, W3O3);
        v[b + 24] = csub(E0, O0);
        v[b + 30] = csub(E1, W1O1);
        v[b + 36] = csub(E2, iO2);
        v[b + 42] = csub(E3, W3O3);
    }

    float2* dstBase = g_bufB + (size_t)sig * NHALF;
#pragma unroll
    for (int m = 0; m < 48; m++) {
        int r6 = 6 * (m & 7);
        float2 acc = v[r6];                              // b=0, W48^0 = 1
#pragma unroll
        for (int b = 1; b < 6; b++)
            cmac(acc, v[r6 + b], sW[(b * m) % 48]);      // compile-time indices
        float2 tw = g_tw48000[k2 * m];                   // k2*m <= 46953 < 48000; 1/48000 folded
        dstBase[m * 1000 + k2] = cmul(acc, tw);
    }
}

// ---------------------------------------------------------------------------
// K3: stage 2 — 1000-point inverse DFT per (sig,m1) row, as a self-sorting
// 3-pass radix-10 Stockham in smem (sign +). Pass (nn, m, s) in
// {(1000,100,1), (100,10,10), (10,1,100)}; for all passes m*s = 100 and the
// group base address equals the group id, so inputs are X[g + 100*r] and:
//   u_j = sum_r X[g+100r] * w10^{j r},  Y[out(g,j)] = u_j * W_nn^{p j}
// Twiddle indices (1000/nn)*p*j < 1000 -> exact g_tw1000 lookup.
// 200 active threads: thread = (group g = tid>>1, j-half = (tid&1)*5).
// ---------------------------------------------------------------------------
__global__ void __launch_bounds__(256) k_stage2() {
    __shared__ float2 sa[1000];
    __shared__ float2 sb[1000];
    __shared__ float2 sW10[10];
    int tid = threadIdx.x;
    int m1  = blockIdx.x;   // 0..47
    int sig = blockIdx.y;   // 0..255

    if (tid < 10) sW10[tid] = g_tw10[tid];
    const float2* src = g_bufB + ((size_t)sig * 48 + m1) * 1000;
    for (int i = tid; i < 1000; i += 256) sa[i] = src[i];
    __syncthreads();

    bool act = (tid < 200);
    int g = tid >> 1;            // group 0..99
    int jb = (tid & 1) * 5;      // j base: 0 or 5
    int p1 = g / 10;             // p for pass 1

    // ---- pass 0: nn=1000, s=1, p=g, out = 10g+j, twidx = g*j
    if (act) {
        float2 in[10];
#pragma unroll
        for (int r = 0; r < 10; r++) in[r] = sa[g + 100 * r];
#pragma unroll
        for (int jj = 0; jj < 5; jj++) {
            int j = jb + jj;
            float2 acc = in[0];
            int t = j;
#pragma unroll
            for (int r = 1; r < 10; r++) {
                cmac(acc, in[r], sW10[t]);
                t += j; if (t >= 10) t -= 10;
            }
            sb[10 * g + j] = cmul(acc, __ldg(&g_tw1000[g * j]));
        }
    }
    __syncthreads();

    // ---- pass 1: nn=100, s=10, p=g/10, out = g + 90p + 10j, twidx = 10*p*j
    if (act) {
        float2 in[10];
#pragma unroll
        for (int r = 0; r < 10; r++) in[r] = sb[g + 100 * r];
#pragma unroll
        for (int jj = 0; jj < 5; jj++) {
            int j = jb + jj;
            float2 acc = in[0];
            int t = j;
#pragma unroll
            for (int r = 1; r < 10; r++) {
                cmac(acc, in[r], sW10[t]);
                t += j; if (t >= 10) t -= 10;
            }
            sa[g + 90 * p1 + 10 * j] = cmul(acc, __ldg(&g_tw1000[10 * p1 * j]));
        }
    }
    __syncthreads();

    // ---- pass 2: nn=10, s=100, p=0, out = g + 100j, twiddle = 1
    if (act) {
        float2 in[10];
#pragma unroll
        for (int r = 0; r < 10; r++) in[r] = sa[g + 100 * r];
#pragma unroll
        for (int jj = 0; jj < 5; jj++) {
            int j = jb + jj;
            float2 acc = in[0];
            int t = j;
#pragma unroll
            for (int r = 1; r < 10; r++) {
                cmac(acc, in[r], sW10[t]);
                t += j; if (t >= 10) t -= 10;
            }
            sb[g + 100 * j] = acc;
        }
    }
    __syncthreads();

    // scatter to natural time order: y[m1 + 48*m2]
    float2* dst = g_bufA + (size_t)sig * NHALF;
    for (int m = tid; m < 1000; m += 256) dst[m1 + 48 * m] = sb[m];
}

// ---------------------------------------------------------------------------
// K4: STFT frame power. Table-twiddle Stockham radix-2 FFT-256, fully
// unrolled passes; q + s*p == tid so butterfly addressing is trivial.
// ---------------------------------------------------------------------------
__global__ void __launch_bounds__(128) k_stft() {
    __shared__ float2 sa[256];
    __shared__ float2 sb[256];
    __shared__ float2 stw[128];
    int tid = threadIdx.x;
    int fr  = blockIdx.x;
    int sig = blockIdx.y;

    stw[tid] = g_tw256[tid];

    const float2* src = g_bufA + (size_t)sig * NHALF + 128 * fr;
#pragma unroll
    for (int h = 0; h < 2; h++) {
        int i = tid + 128 * h;
        float2 y = src[i];
        float2 w = g_hann2[i];
        sa[i] = make_float2(y.x * w.x, y.y * w.y);
    }
    __syncthreads();

    float2* X = sa;
    float2* Y = sb;
#pragma unroll
    for (int i = 0; i < 8; i++) {
        int s  = 1 << i;
        int lo = tid & (s - 1);
        int hi = tid ^ lo;                  // = (tid>>i)<<i
        float2 a = X[tid];
        float2 b = X[tid + 128];
        float2 w = stw[hi];                 // e^{-2pi i p/nn}
        int o = (hi << 1) | lo;
        Y[o] = make_float2(a.x + b.x, a.y + b.y);
        float dx = a.x - b.x, dy = a.y - b.y;
        Y[o + s] = make_float2(dx * w.x - dy * w.y, dx * w.y + dy * w.x);
        __syncthreads();
        float2* tmp = X; X = Y; Y = tmp;
    }
    // 8 swaps -> result back in sa (== X)

    float* Pout = g_P + ((size_t)sig * TFRAMES + fr) * FBINS;
#pragma unroll
    for (int h = 0; h < 2; h++) {
        int f = tid + 128 * h;
        float2 z1 = X[f];
        float2 z2 = X[(256 - f) & 255]; z2.y = -z2.y;
        float Ex = 0.5f * (z1.x + z2.x), Ey = 0.5f * (z1.y + z2.y);
        float Dx = 0.5f * (z1.x - z2.x), Dy = 0.5f * (z1.y - z2.y);
        float Ox = Dy, Oy = -Dx;                       // O = D / i
        float2 tw = __ldg(&g_tw512[f]);                // e^{-2pi i f/512}
        float Sx = Ex + Ox * tw.x - Oy * tw.y;
        float Sy = Ey + Ox * tw.y + Oy * tw.x;
        Pout[f] = Sx * Sx + Sy * Sy;
    }
    if (tid == 0) {
        float v = X[0].x - X[0].y;                     // Nyquist: E[0] - O[0]
        Pout[256] = v * v;
    }
}

// ---------------------------------------------------------------------------
// K5: per-pair EDR + loss partials (deterministic block reduction).
// ---------------------------------------------------------------------------
__global__ void __launch_bounds__(512) k_loss() {
    __shared__ float sn[512], sd[512];
    int tid = threadIdx.x;
    int s   = blockIdx.x;                       // 0..127
    float num = 0.f, den = 0.f;
    if (tid < FBINS) {
        const float* pt = g_P + (size_t)s * TFRAMES * FBINS + tid;
        const float* pa = g_P + (size_t)(s + 128) * TFRAMES * FBINS + tid;
        float st = 0.f, sv = 0.f;
        for (int t = TFRAMES - 1; t >= 0; --t) {
            st += pt[t * FBINS];
            sv += pa[t * FBINS];
            float et = 10.f * log10f(st);
            float ea = 10.f * log10f(sv);
            num += fabsf(et - ea);
            den += fabsf(et);
        }
    }
    sn[tid] = num; sd[tid] = den;
    __syncthreads();
    for (int off = 256; off > 0; off >>= 1) {
        if (tid < off) { sn[tid] += sn[tid + off]; sd[tid] += sd[tid + off]; }
        __syncthreads();
    }
    if (tid == 0) {
        g_partial[2 * s]     = sn[0];
        g_partial[2 * s + 1] = sd[0];
    }
}

__global__ void k_final(float* __restrict__ out) {
    double n = 0.0, d = 0.0;
    for (int i = 0; i < 128; i++) {
        n += (double)g_partial[2 * i];
        d += (double)g_partial[2 * i + 1];
    }
    out[0] = (float)(n / d);
}

// ---------------------------------------------------------------------------
extern "C" void kernel_launch(void* const* d_in, const int* in_sizes, int n_in,
                              void* d_out, int out_size) {
    const float* tre = (const float*)d_in[0];
    const float* tim = (const float*)d_in[1];
    const float* are = (const float*)d_in[2];
    const float* aim = (const float*)d_in[3];

    k_setup <<<94, 512>>>();
    k_pack  <<<dim3(375, NSIG), 128>>>(tre, tim, are, aim);
    k_stage1<<<dim3(8,   NSIG), 125>>>();
    k_stage2<<<dim3(48,  NSIG), 256>>>();
    k_stft  <<<dim3(TFRAMES, NSIG), 128>>>();
    k_loss  <<<128, 512>>>();
    k_final <<<1, 1>>>((float*)d_out);
}

// round 6
// speedup vs baseline: 2.1726x; 1.3428x over previous
#include <cuda_runtime.h>
#include <math.h>

// ---------------------------------------------------------------------------
// EDR loss pipeline (round 5: kill scattered twiddle LDGs):
//   irfft(96000) via pack trick -> complex IFFT(48000) = 48 (=8x6, regs) x 1000 (=10^3, smem)
//   -> Hann STFT (512/256, 374 frames) via radix-4 Stockham FFT-256 (2 frames/CTA)
//   -> power -> suffix-sum over frames -> 10*log10 -> sum|dt-da| / sum|dt|
// ---------------------------------------------------------------------------

#define NSIG     256
#define NHALF    48000
#define ROWLEN   96000
#define TFRAMES  374
#define FBINS    257

// scratch (allowed: __device__ globals)
__device__ float2 g_bufA[NSIG * NHALF];
__device__ float2 g_bufB[NSIG * NHALF];
__device__ float  g_P[NSIG * TFRAMES * FBINS];
__device__ float  g_partial[256];

// twiddle tables (filled by k_setup every launch; deterministic)
__device__ float2 g_twpack[48000];    // e^{+2pi i k/96000}  (pack kernel)
__device__ float2 g_tw1000[1000];     // e^{+2pi i t/1000}
__device__ float2 g_tw48[48];         // e^{+2pi i t/48}
__device__ float2 g_tw10[10];         // e^{+2pi i t/10}
__device__ float2 g_tw256f[256];      // e^{-2pi i t/256}
__device__ float2 g_tw512[256];       // e^{-2pi i f/512}
__device__ float2 g_hann2[256];       // (hann(2i), hann(2i+1)), periodic Hann 512

__device__ __forceinline__ void cmac(float2& acc, float2 a, float2 w) {
    acc.x += a.x * w.x - a.y * w.y;
    acc.y += a.x * w.y + a.y * w.x;
}
__device__ __forceinline__ float2 cadd(float2 a, float2 b){ return make_float2(a.x+b.x, a.y+b.y); }
__device__ __forceinline__ float2 csub(float2 a, float2 b){ return make_float2(a.x-b.x, a.y-b.y); }
__device__ __forceinline__ float2 cmul(float2 a, float2 b){
    return make_float2(a.x*b.x - a.y*b.y, a.x*b.y + a.y*b.x);
}
__device__ __forceinline__ float2 cmuli(float2 a){ return make_float2(-a.y, a.x); }  // i*a

// ---------------------------------------------------------------------------
__global__ void __launch_bounds__(512) k_setup() {
    int t = blockIdx.x * 512 + threadIdx.x;
    float s, c;
    if (t < 48000) {
        sincosf((float)t * 6.5449846949787352e-5f, &s, &c);   // +2pi/96000
        g_twpack[t] = make_float2(c, s);
    }
    if (t < 1000) {
        sincosf((float)t * 6.2831853071795865e-3f, &s, &c);   // +2pi/1000
        g_tw1000[t] = make_float2(c, s);
    }
    if (t < 48) {
        sincosf((float)t * 0.13089969389957472f, &s, &c);     // +2pi/48
        g_tw48[t] = make_float2(c, s);
    }
    if (t < 10) {
        sincosf((float)t * 0.62831853071795865f, &s, &c);     // +2pi/10
        g_tw10[t] = make_float2(c, s);
    }
    if (t < 256) {
        sincosf(-(float)t * 2.4543692606170259e-2f, &s, &c);  // -2pi/256
        g_tw256f[t] = make_float2(c, s);
        sincosf(-(float)t * 1.2271846303085130e-2f, &s, &c);  // -2pi/512
        g_tw512[t] = make_float2(c, s);
        float w0 = 0.5f - 0.5f * cosf((float)(2 * t)     * 1.2271846303085130e-2f);
        float w1 = 0.5f - 0.5f * cosf((float)(2 * t + 1) * 1.2271846303085130e-2f);
        g_hann2[t] = make_float2(w0, w1);
    }
}

// ---------------------------------------------------------------------------
// K1: packed spectrum Y[k] = E[k] + i*O[k] for the length-48000 complex IFFT.
// ---------------------------------------------------------------------------
__global__ void __launch_bounds__(128) k_pack(const float* __restrict__ tre,
                                              const float* __restrict__ tim,
                                              const float* __restrict__ are,
                                              const float* __restrict__ aim) {
    int k   = blockIdx.x * 128 + threadIdx.x;   // 0..47999
    int sig = blockIdx.y;
    const float* re = (sig < 128 ? tre : are) + (size_t)(sig & 127) * ROWLEN;
    const float* im = (sig < 128 ? tim : aim) + (size_t)(sig & 127) * ROWLEN;

    float2 Y;
    if (k == 0) {
        float r0 = re[0], rM = re[NHALF];
        Y = make_float2(0.5f * (r0 + rM), 0.5f * (r0 - rM));
    } else {
        float ar = re[k],         ai = im[k];
        float br = re[NHALF - k], bi = -im[NHALF - k];
        float Ex = 0.5f * (ar + br), Ey = 0.5f * (ai + bi);
        float Dx = 0.5f * (ar - br), Dy = 0.5f * (ai - bi);
        float2 w = __ldg(&g_twpack[k]);                      // e^{+2pi i k/96000}
        float Ox = w.x * Dx - w.y * Dy;
        float Oy = w.x * Dy + w.y * Dx;
        Y = make_float2(Ex - Oy, Ey + Ox);
    }
    g_bufA[(size_t)sig * NHALF + k] = Y;
}

// ---------------------------------------------------------------------------
// K2: stage 1 of IFFT-48000. One thread per k2; 48-point DFT over k1 as 8x6
// Cooley-Tukey in registers; final twiddle e^{+2pi i k2 m/48000}/48000 via a
// per-thread complex recurrence (w *= wstep) instead of scattered LDGs.
// ---------------------------------------------------------------------------
__global__ void __launch_bounds__(125) k_stage1() {
    __shared__ float2 sW[48];
    int tid = threadIdx.x;               // 0..124
    int sig = blockIdx.y;
    int k2  = blockIdx.x * 125 + tid;    // 8 blocks * 125 = 1000

    if (tid < 48) sW[tid] = g_tw48[tid];
    __syncthreads();

    const float2* src = g_bufA + (size_t)sig * NHALF;
    float2 v[48];
#pragma unroll
    for (int k1 = 0; k1 < 48; k1++) v[k1] = src[k2 + 1000 * k1];

    // six DFT-8s (positive exponent), in place: v[6r+b] = F_b[r]
    const float C = 0.70710678118654752f;
#pragma unroll
    for (int b = 0; b < 6; b++) {
        float2 x0 = v[b],      x1 = v[b + 6],  x2 = v[b + 12], x3 = v[b + 18];
        float2 x4 = v[b + 24], x5 = v[b + 30], x6 = v[b + 36], x7 = v[b + 42];
        float2 g0 = cadd(x0, x4), g1 = csub(x0, x4);
        float2 g2 = cadd(x2, x6), g3 = csub(x2, x6);
        float2 h0 = cadd(x1, x5), h1 = csub(x1, x5);
        float2 h2 = cadd(x3, x7), h3 = csub(x3, x7);
        float2 ig3 = cmuli(g3), ih3 = cmuli(h3);
        float2 E0 = cadd(g0, g2), E2 = csub(g0, g2);
        float2 E1 = cadd(g1, ig3), E3 = csub(g1, ig3);
        float2 O0 = cadd(h0, h2), O2 = csub(h0, h2);
        float2 O1 = cadd(h1, ih3), O3 = csub(h1, ih3);
        float2 W1O1 = make_float2(C * (O1.x - O1.y),  C * (O1.x + O1.y));   // e^{+i pi/4}  * O1
        float2 W3O3 = make_float2(-C * (O3.x + O3.y), C * (O3.x - O3.y));   // e^{+i 3pi/4} * O3
        float2 iO2  = cmuli(O2);
        v[b]      = cadd(E0, O0);
        v[b + 6]  = cadd(E1, W1O1);
        v[b + 12] = cadd(E2, iO2);
        v[b + 18] = cadd(E3, W3O3);
        v[b + 24] = csub(E0, O0);
        v[b + 30] = csub(E1, W1O1);
        v[b + 36] = csub(E2, iO2);
        v[b + 42] = csub(E3, W3O3);
    }

    // per-thread twiddle recurrence: w_m = (1/48000) * e^{+2pi i k2 m/48000}
    float sn, cs;
    sincosf((float)k2 * 1.3089969389957471e-4f, &sn, &cs);   // +2pi*k2/48000
    float2 wstep = make_float2(cs, sn);
    float2 w = make_float2(1.0f / 48000.0f, 0.0f);

    float2* dstBase = g_bufB + (size_t)sig * NHALF;
#pragma unroll
    for (int m = 0; m < 48; m++) {
        int r6 = 6 * (m & 7);
        float2 acc = v[r6];                              // b=0, W48^0 = 1
#pragma unroll
        for (int b = 1; b < 6; b++)
            cmac(acc, v[r6 + b], sW[(b * m) % 48]);      // compile-time indices
        dstBase[m * 1000 + k2] = cmul(acc, w);
        w = cmul(w, wstep);
    }
}

// ---------------------------------------------------------------------------
// K3: stage 2 — 1000-point inverse DFT per (sig,m1) row, 3-pass radix-10
// Stockham in smem (sign +). All twiddles come from an smem copy of g_tw1000.
// ---------------------------------------------------------------------------
__global__ void __launch_bounds__(256) k_stage2() {
    __shared__ float2 sa[1000];
    __shared__ float2 sb[1000];
    __shared__ float2 sTw[1000];
    __shared__ float2 sW10[10];
    int tid = threadIdx.x;
    int m1  = blockIdx.x;   // 0..47
    int sig = blockIdx.y;   // 0..255

    if (tid < 10) sW10[tid] = g_tw10[tid];
    const float2* src = g_bufB + ((size_t)sig * 48 + m1) * 1000;
    for (int i = tid; i < 1000; i += 256) {
        sa[i]  = src[i];
        sTw[i] = g_tw1000[i];
    }
    __syncthreads();

    bool act = (tid < 200);
    int g = tid >> 1;            // group 0..99
    int jb = (tid & 1) * 5;      // j base: 0 or 5
    int p1 = g / 10;             // p for pass 1

    // ---- pass 0: nn=1000, s=1, p=g, out = 10g+j, twidx = g*j
    if (act) {
        float2 in[10];
#pragma unroll
        for (int r = 0; r < 10; r++) in[r] = sa[g + 100 * r];
#pragma unroll
        for (int jj = 0; jj < 5; jj++) {
            int j = jb + jj;
            float2 acc = in[0];
            int t = j;
#pragma unroll
            for (int r = 1; r < 10; r++) {
                cmac(acc, in[r], sW10[t]);
                t += j; if (t >= 10) t -= 10;
            }
            sb[10 * g + j] = cmul(acc, sTw[g * j]);
        }
    }
    __syncthreads();

    // ---- pass 1: nn=100, s=10, p=g/10, out = g + 90p + 10j, twidx = 10*p*j
    if (act) {
        float2 in[10];
#pragma unroll
        for (int r = 0; r < 10; r++) in[r] = sb[g + 100 * r];
#pragma unroll
        for (int jj = 0; jj < 5; jj++) {
            int j = jb + jj;
            float2 acc = in[0];
            int t = j;
#pragma unroll
            for (int r = 1; r < 10; r++) {
                cmac(acc, in[r], sW10[t]);
                t += j; if (t >= 10) t -= 10;
            }
            sa[g + 90 * p1 + 10 * j] = cmul(acc, sTw[10 * p1 * j]);
        }
    }
    __syncthreads();

    // ---- pass 2: nn=10, s=100, p=0, out = g + 100j, twiddle = 1
    if (act) {
        float2 in[10];
#pragma unroll
        for (int r = 0; r < 10; r++) in[r] = sa[g + 100 * r];
#pragma unroll
        for (int jj = 0; jj < 5; jj++) {
            int j = jb + jj;
            float2 acc = in[0];
            int t = j;
#pragma unroll
            for (int r = 1; r < 10; r++) {
                cmac(acc, in[r], sW10[t]);
                t += j; if (t >= 10) t -= 10;
            }
            sb[g + 100 * j] = acc;
        }
    }
    __syncthreads();

    // scatter to natural time order: y[m1 + 48*m2]
    float2* dst = g_bufA + (size_t)sig * NHALF;
    for (int m = tid; m < 1000; m += 256) dst[m1 + 48 * m] = sb[m];
}

// ---------------------------------------------------------------------------
// K4: STFT frame power. Radix-4 Stockham FFT-256 (sign -), 2 frames per CTA,
// 4 passes / 4 barriers, smem twiddle table. Then rfft unpack -> |.|^2.
// ---------------------------------------------------------------------------
__global__ void __launch_bounds__(128) k_stft() {
    __shared__ float2 sA[2][256];
    __shared__ float2 sB[2][256];
    __shared__ float2 stw[256];
    int tid = threadIdx.x;
    int lf  = tid >> 6;          // local frame 0/1
    int g   = tid & 63;          // group within frame
    int fr  = blockIdx.x * 2 + lf;
    int sig = blockIdx.y;

    for (int i = tid; i < 256; i += 128) stw[i] = g_tw256f[i];

    const float2* src = g_bufA + (size_t)sig * NHALF + 128 * fr;
#pragma unroll
    for (int h = 0; h < 4; h++) {
        int i = g + 64 * h;
        float2 y = src[i];
        float2 w = g_hann2[i];
        sA[lf][i] = make_float2(y.x * w.x, y.y * w.y);
    }
    __syncthreads();

    float2* X = sA[lf];
    float2* Y = sB[lf];
#pragma unroll
    for (int pass = 0; pass < 4; pass++) {
        int s = 1 << (2 * pass);            // 1,4,16,64 ; m = 64/s ; s*m = 64
        int q = g & (s - 1);
        int p = g >> (2 * pass);
        float2 x0 = X[g], x1 = X[g + 64], x2 = X[g + 128], x3 = X[g + 192];
        float2 t0 = cadd(x0, x2), t1 = csub(x0, x2);
        float2 t2 = cadd(x1, x3), t3 = csub(x1, x3);
        float2 it3 = cmuli(t3);
        float2 u0 = cadd(t0, t2);
        float2 u2 = csub(t0, t2);
        float2 u1 = csub(t1, it3);          // x0 - i x1 - x2 + i x3
        float2 u3 = cadd(t1, it3);          // x0 + i x1 - x2 - i x3
        int base = p * s;                   // twiddle idx = p*j*(256/nn) = p*j*s
        u1 = cmul(u1, stw[base]);
        u2 = cmul(u2, stw[2 * base]);
        u3 = cmul(u3, stw[3 * base]);
        int o = q + 4 * p * s;              // out: q + s*(4p + j)
        Y[o]         = u0;
        Y[o + s]     = u1;
        Y[o + 2 * s] = u2;
        Y[o + 3 * s] = u3;
        __syncthreads();
        float2* tmp = X; X = Y; Y = tmp;
    }
    // 4 swaps -> result back in sA[lf] (== X), natural order

    float* Pout = g_P + ((size_t)sig * TFRAMES + fr) * FBINS;
#pragma unroll
    for (int h = 0; h < 4; h++) {
        int f = g + 64 * h;
        float2 z1 = X[f];
        float2 z2 = X[(256 - f) & 255]; z2.y = -z2.y;
        float Ex = 0.5f * (z1.x + z2.x), Ey = 0.5f * (z1.y + z2.y);
        float Dx = 0.5f * (z1.x - z2.x), Dy = 0.5f * (z1.y - z2.y);
        float Ox = Dy, Oy = -Dx;                       // O = D / i
        float2 tw = __ldg(&g_tw512[f]);                // e^{-2pi i f/512}
        float Sx = Ex + Ox * tw.x - Oy * tw.y;
        float Sy = Ey + Ox * tw.y + Oy * tw.x;
        Pout[f] = Sx * Sx + Sy * Sy;
    }
    if (g == 0) {
        float v = X[0].x - X[0].y;                     // Nyquist: E[0] - O[0]
        Pout[256] = v * v;
    }
}

// ---------------------------------------------------------------------------
// K5: per-pair EDR + loss partials (deterministic block reduction).
// 10*log10(x) = (10/log2(10)) * log2(x), via MUFU __log2f.
// ---------------------------------------------------------------------------
__global__ void __launch_bounds__(512) k_loss() {
    __shared__ float sn[512], sd[512];
    int tid = threadIdx.x;
    int s   = blockIdx.x;                       // 0..127
    const float K = 3.0102999566398120f;        // 10 / log2(10)
    float num = 0.f, den = 0.f;
    if (tid < FBINS) {
        const float* pt = g_P + (size_t)s * TFRAMES * FBINS + tid;
        const float* pa = g_P + (size_t)(s + 128) * TFRAMES * FBINS + tid;
        float st = 0.f, sv = 0.f;
        for (int t = TFRAMES - 1; t >= 0; --t) {
            st += pt[t * FBINS];
            sv += pa[t * FBINS];
            float et = K * __log2f(st);
            float ea = K * __log2f(sv);
            num += fabsf(et - ea);
            den += fabsf(et);
        }
    }
    sn[tid] = num; sd[tid] = den;
    __syncthreads();
    for (int off = 256; off > 0; off >>= 1) {
        if (tid < off) { sn[tid] += sn[tid + off]; sd[tid] += sd[tid + off]; }
        __syncthreads();
    }
    if (tid == 0) {
        g_partial[2 * s]     = sn[0];
        g_partial[2 * s + 1] = sd[0];
    }
}

__global__ void k_final(float* __restrict__ out) {
    double n = 0.0, d = 0.0;
    for (int i = 0; i < 128; i++) {
        n += (double)g_partial[2 * i];
        d += (double)g_partial[2 * i + 1];
    }
    out[0] = (float)(n / d);
}

// ---------------------------------------------------------------------------
extern "C" void kernel_launch(void* const* d_in, const int* in_sizes, int n_in,
                              void* d_out, int out_size) {
    const float* tre = (const float*)d_in[0];
    const float* tim = (const float*)d_in[1];
    const float* are = (const float*)d_in[2];
    const float* aim = (const float*)d_in[3];

    k_setup <<<94, 512>>>();
    k_pack  <<<dim3(375, NSIG), 128>>>(tre, tim, are, aim);
    k_stage1<<<dim3(8,   NSIG), 125>>>();
    k_stage2<<<dim3(48,  NSIG), 256>>>();
    k_stft  <<<dim3(187, NSIG), 128>>>();
    k_loss  <<<128, 512>>>();
    k_final <<<1, 1>>>((float*)d_out);
}

// round 7
// speedup vs baseline: 2.5757x; 1.1855x over previous
#include <cuda_runtime.h>
#include <math.h>

// ---------------------------------------------------------------------------
// EDR loss pipeline (round 6: stage2 -> thread-per-group streaming accumulators):
//   irfft(96000) via pack trick -> complex IFFT(48000) = 48 (=8x6, regs) x 1000 (=10^3, smem)
//   -> Hann STFT (512/256, 374 frames) via radix-4 Stockham FFT-256 (2 frames/CTA)
//   -> power -> suffix-sum over frames -> 10*log10 -> sum|dt-da| / sum|dt|
// ---------------------------------------------------------------------------

#define NSIG     256
#define NHALF    48000
#define ROWLEN   96000
#define TFRAMES  374
#define FBINS    257

// scratch (allowed: __device__ globals)
__device__ float2 g_bufA[NSIG * NHALF];
__device__ float2 g_bufB[NSIG * NHALF];
__device__ float  g_P[NSIG * TFRAMES * FBINS];
__device__ float  g_partial[256];

// twiddle tables (filled by k_setup every launch; deterministic)
__device__ float2 g_twpack[48000];    // e^{+2pi i k/96000}  (pack kernel)
__device__ float2 g_tw1000[1000];     // e^{+2pi i t/1000}
__device__ float2 g_tw48[48];         // e^{+2pi i t/48}
__device__ float2 g_tw10[10];         // e^{+2pi i t/10}
__device__ float2 g_tw256f[256];      // e^{-2pi i t/256}
__device__ float2 g_tw512[256];       // e^{-2pi i f/512}
__device__ float2 g_hann2[256];       // (hann(2i), hann(2i+1)), periodic Hann 512

__device__ __forceinline__ void cmac(float2& acc, float2 a, float2 w) {
    acc.x += a.x * w.x - a.y * w.y;
    acc.y += a.x * w.y + a.y * w.x;
}
__device__ __forceinline__ float2 cadd(float2 a, float2 b){ return make_float2(a.x+b.x, a.y+b.y); }
__device__ __forceinline__ float2 csub(float2 a, float2 b){ return make_float2(a.x-b.x, a.y-b.y); }
__device__ __forceinline__ float2 cmul(float2 a, float2 b){
    return make_float2(a.x*b.x - a.y*b.y, a.x*b.y + a.y*b.x);
}
__device__ __forceinline__ float2 cmuli(float2 a){ return make_float2(-a.y, a.x); }  // i*a

// ---------------------------------------------------------------------------
__global__ void __launch_bounds__(512) k_setup() {
    int t = blockIdx.x * 512 + threadIdx.x;
    float s, c;
    if (t < 48000) {
        sincosf((float)t * 6.5449846949787352e-5f, &s, &c);   // +2pi/96000
        g_twpack[t] = make_float2(c, s);
    }
    if (t < 1000) {
        sincosf((float)t * 6.2831853071795865e-3f, &s, &c);   // +2pi/1000
        g_tw1000[t] = make_float2(c, s);
    }
    if (t < 48) {
        sincosf((float)t * 0.13089969389957472f, &s, &c);     // +2pi/48
        g_tw48[t] = make_float2(c, s);
    }
    if (t < 10) {
        sincosf((float)t * 0.62831853071795865f, &s, &c);     // +2pi/10
        g_tw10[t] = make_float2(c, s);
    }
    if (t < 256) {
        sincosf(-(float)t * 2.4543692606170259e-2f, &s, &c);  // -2pi/256
        g_tw256f[t] = make_float2(c, s);
        sincosf(-(float)t * 1.2271846303085130e-2f, &s, &c);  // -2pi/512
        g_tw512[t] = make_float2(c, s);
        float w0 = 0.5f - 0.5f * cosf((float)(2 * t)     * 1.2271846303085130e-2f);
        float w1 = 0.5f - 0.5f * cosf((float)(2 * t + 1) * 1.2271846303085130e-2f);
        g_hann2[t] = make_float2(w0, w1);
    }
}

// ---------------------------------------------------------------------------
// K1: packed spectrum Y[k] = E[k] + i*O[k] for the length-48000 complex IFFT.
// ---------------------------------------------------------------------------
__global__ void __launch_bounds__(128) k_pack(const float* __restrict__ tre,
                                              const float* __restrict__ tim,
                                              const float* __restrict__ are,
                                              const float* __restrict__ aim) {
    int k   = blockIdx.x * 128 + threadIdx.x;   // 0..47999
    int sig = blockIdx.y;
    const float* re = (sig < 128 ? tre : are) + (size_t)(sig & 127) * ROWLEN;
    const float* im = (sig < 128 ? tim : aim) + (size_t)(sig & 127) * ROWLEN;

    float2 Y;
    if (k == 0) {
        float r0 = re[0], rM = re[NHALF];
        Y = make_float2(0.5f * (r0 + rM), 0.5f * (r0 - rM));
    } else {
        float ar = re[k],         ai = im[k];
        float br = re[NHALF - k], bi = -im[NHALF - k];
        float Ex = 0.5f * (ar + br), Ey = 0.5f * (ai + bi);
        float Dx = 0.5f * (ar - br), Dy = 0.5f * (ai - bi);
        float2 w = __ldg(&g_twpack[k]);                      // e^{+2pi i k/96000}
        float Ox = w.x * Dx - w.y * Dy;
        float Oy = w.x * Dy + w.y * Dx;
        Y = make_float2(Ex - Oy, Ey + Ox);
    }
    g_bufA[(size_t)sig * NHALF + k] = Y;
}

// ---------------------------------------------------------------------------
// K2: stage 1 of IFFT-48000. One thread per k2; 48-point DFT over k1 as 8x6
// Cooley-Tukey in registers; final twiddle e^{+2pi i k2 m/48000}/48000 via a
// per-thread complex recurrence (w *= wstep) instead of scattered LDGs.
// ---------------------------------------------------------------------------
__global__ void __launch_bounds__(125) k_stage1() {
    __shared__ float2 sW[48];
    int tid = threadIdx.x;               // 0..124
    int sig = blockIdx.y;
    int k2  = blockIdx.x * 125 + tid;    // 8 blocks * 125 = 1000

    if (tid < 48) sW[tid] = g_tw48[tid];
    __syncthreads();

    const float2* src = g_bufA + (size_t)sig * NHALF;
    float2 v[48];
#pragma unroll
    for (int k1 = 0; k1 < 48; k1++) v[k1] = src[k2 + 1000 * k1];

    // six DFT-8s (positive exponent), in place: v[6r+b] = F_b[r]
    const float C = 0.70710678118654752f;
#pragma unroll
    for (int b = 0; b < 6; b++) {
        float2 x0 = v[b],      x1 = v[b + 6],  x2 = v[b + 12], x3 = v[b + 18];
        float2 x4 = v[b + 24], x5 = v[b + 30], x6 = v[b + 36], x7 = v[b + 42];
        float2 g0 = cadd(x0, x4), g1 = csub(x0, x4);
        float2 g2 = cadd(x2, x6), g3 = csub(x2, x6);
        float2 h0 = cadd(x1, x5), h1 = csub(x1, x5);
        float2 h2 = cadd(x3, x7), h3 = csub(x3, x7);
        float2 ig3 = cmuli(g3), ih3 = cmuli(h3);
        float2 E0 = cadd(g0, g2), E2 = csub(g0, g2);
        float2 E1 = cadd(g1, ig3), E3 = csub(g1, ig3);
        float2 O0 = cadd(h0, h2), O2 = csub(h0, h2);
        float2 O1 = cadd(h1, ih3), O3 = csub(h1, ih3);
        float2 W1O1 = make_float2(C * (O1.x - O1.y),  C * (O1.x + O1.y));   // e^{+i pi/4}  * O1
        float2 W3O3 = make_float2(-C * (O3.x + O3.y), C * (O3.x - O3.y));   // e^{+i 3pi/4} * O3
        float2 iO2  = cmuli(O2);
        v[b]      = cadd(E0, O0);
        v[b + 6]  = cadd(E1, W1O1);
        v[b + 12] = cadd(E2, iO2);
        v[b + 18] = cadd(E3, W3O3);
        v[b + 24] = csub(E0, O0);
        v[b + 30] = csub(E1, W1O1);
        v[b + 36] = csub(E2, iO2);
        v[b + 42] = csub(E3, W3O3);
    }

    // per-thread twiddle recurrence: w_m = (1/48000) * e^{+2pi i k2 m/48000}
    float sn, cs;
    sincosf((float)k2 * 1.3089969389957471e-4f, &sn, &cs);   // +2pi*k2/48000
    float2 wstep = make_float2(cs, sn);
    float2 w = make_float2(1.0f / 48000.0f, 0.0f);

    float2* dstBase = g_bufB + (size_t)sig * NHALF;
#pragma unroll
    for (int m = 0; m < 48; m++) {
        int r6 = 6 * (m & 7);
        float2 acc = v[r6];                              // b=0, W48^0 = 1
#pragma unroll
        for (int b = 1; b < 6; b++)
            cmac(acc, v[r6 + b], sW[(b * m) % 48]);      // compile-time indices
        dstBase[m * 1000 + k2] = cmul(acc, w);
        w = cmul(w, wstep);
    }
}

// ---------------------------------------------------------------------------
// K3: stage 2 — 1000-point inverse DFT per (sig,m1) row, 3-pass radix-10
// Stockham (sign +). Thread g (<100) owns one butterfly group and all 10 of
// its outputs (register accumulators); sW10 indices are compile-time.
// Pass 0 streams inputs straight from global (coalesced: lane = g), pass 2
// writes results straight to global. Output twiddles by complex recurrence
// (w *= base), base from one g_tw1000 lookup. Only 3 barriers, 16KB smem.
// ---------------------------------------------------------------------------
__global__ void __launch_bounds__(128) k_stage2() {
    __shared__ float2 sA[1000];
    __shared__ float2 sB[1000];
    __shared__ float2 sW10[10];
    int tid = threadIdx.x;
    int m1  = blockIdx.x;   // 0..47
    int sig = blockIdx.y;   // 0..255

    if (tid < 10) sW10[tid] = g_tw10[tid];

    bool act = (tid < 100);
    int g = tid;
    int p1 = g / 10;

    const float2* src = g_bufB + ((size_t)sig * 48 + m1) * 1000;
    float2 in[10];
    float2 wg = make_float2(1.f, 0.f), wp = make_float2(1.f, 0.f);
    if (act) {
#pragma unroll
        for (int r = 0; r < 10; r++) in[r] = __ldg(&src[g + 100 * r]);   // coalesced
        wg = __ldg(&g_tw1000[g]);          // e^{+2pi i g/1000}
        wp = __ldg(&g_tw1000[10 * p1]);    // e^{+2pi i p1/100}
    }
    __syncthreads();   // publish sW10 (overlaps the LDG latency above)

    float2 acc[10];

    // ---- pass 0: nn=1000, s=1, p=g: out[10g+j] = tw^{g j} * sum_r in[r] w10^{rj}
    if (act) {
#pragma unroll
        for (int j = 0; j < 10; j++) acc[j] = in[0];
#pragma unroll
        for (int r = 1; r < 10; r++) {
#pragma unroll
            for (int j = 0; j < 10; j++) cmac(acc[j], in[r], sW10[(r * j) % 10]);
        }
        float2 w = make_float2(1.f, 0.f);
        sB[10 * g] = acc[0];
#pragma unroll
        for (int j = 1; j < 10; j++) {
            w = cmul(w, wg);
            sB[10 * g + j] = cmul(acc[j], w);
        }
    }
    __syncthreads();

    // ---- pass 1: nn=100, s=10, p=p1: out[g + 90 p1 + 10j], tw = wp^j
    if (act) {
#pragma unroll
        for (int r = 0; r < 10; r++) in[r] = sB[g + 100 * r];
#pragma unroll
        for (int j = 0; j < 10; j++) acc[j] = in[0];
#pragma unroll
        for (int r = 1; r < 10; r++) {
#pragma unroll
            for (int j = 0; j < 10; j++) cmac(acc[j], in[r], sW10[(r * j) % 10]);
        }
        int ob = g + 90 * p1;
        float2 w = make_float2(1.f, 0.f);
        sA[ob] = acc[0];
#pragma unroll
        for (int j = 1; j < 10; j++) {
            w = cmul(w, wp);
            sA[ob + 10 * j] = cmul(acc[j], w);
        }
    }
    __syncthreads();

    // ---- pass 2: nn=10, s=100, p=0: out[g + 100j], no twiddle; straight to gmem
    if (act) {
#pragma unroll
        for (int r = 0; r < 10; r++) in[r] = sA[g + 100 * r];
#pragma unroll
        for (int j = 0; j < 10; j++) acc[j] = in[0];
#pragma unroll
        for (int r = 1; r < 10; r++) {
#pragma unroll
            for (int j = 0; j < 10; j++) cmac(acc[j], in[r], sW10[(r * j) % 10]);
        }
        float2* dst = g_bufA + (size_t)sig * NHALF + m1;   // y[m1 + 48*m2]
#pragma unroll
        for (int j = 0; j < 10; j++) dst[48 * (g + 100 * j)] = acc[j];
    }
}

// ---------------------------------------------------------------------------
// K4: STFT frame power. Radix-4 Stockham FFT-256 (sign -), 2 frames per CTA,
// 4 passes / 4 barriers, smem twiddle table. Then rfft unpack -> |.|^2.
// ---------------------------------------------------------------------------
__global__ void __launch_bounds__(128) k_stft() {
    __shared__ float2 sA[2][256];
    __shared__ float2 sB[2][256];
    __shared__ float2 stw[256];
    int tid = threadIdx.x;
    int lf  = tid >> 6;          // local frame 0/1
    int g   = tid & 63;          // group within frame
    int fr  = blockIdx.x * 2 + lf;
    int sig = blockIdx.y;

    for (int i = tid; i < 256; i += 128) stw[i] = g_tw256f[i];

    const float2* src = g_bufA + (size_t)sig * NHALF + 128 * fr;
#pragma unroll
    for (int h = 0; h < 4; h++) {
        int i = g + 64 * h;
        float2 y = src[i];
        float2 w = g_hann2[i];
        sA[lf][i] = make_float2(y.x * w.x, y.y * w.y);
    }
    __syncthreads();

    float2* X = sA[lf];
    float2* Y = sB[lf];
#pragma unroll
    for (int pass = 0; pass < 4; pass++) {
        int s = 1 << (2 * pass);            // 1,4,16,64
        int q = g & (s - 1);
        int p = g >> (2 * pass);
        float2 x0 = X[g], x1 = X[g + 64], x2 = X[g + 128], x3 = X[g + 192];
        float2 t0 = cadd(x0, x2), t1 = csub(x0, x2);
        float2 t2 = cadd(x1, x3), t3 = csub(x1, x3);
        float2 it3 = cmuli(t3);
        float2 u0 = cadd(t0, t2);
        float2 u2 = csub(t0, t2);
        float2 u1 = csub(t1, it3);
        float2 u3 = cadd(t1, it3);
        int base = p * s;
        u1 = cmul(u1, stw[base]);
        u2 = cmul(u2, stw[2 * base]);
        u3 = cmul(u3, stw[3 * base]);
        int o = q + 4 * p * s;
        Y[o]         = u0;
        Y[o + s]     = u1;
        Y[o + 2 * s] = u2;
        Y[o + 3 * s] = u3;
        __syncthreads();
        float2* tmp = X; X = Y; Y = tmp;
    }

    float* Pout = g_P + ((size_t)sig * TFRAMES + fr) * FBINS;
#pragma unroll
    for (int h = 0; h < 4; h++) {
        int f = g + 64 * h;
        float2 z1 = X[f];
        float2 z2 = X[(256 - f) & 255]; z2.y = -z2.y;
        float Ex = 0.5f * (z1.x + z2.x), Ey = 0.5f * (z1.y + z2.y);
        float Dx = 0.5f * (z1.x - z2.x), Dy = 0.5f * (z1.y - z2.y);
        float Ox = Dy, Oy = -Dx;                       // O = D / i
        float2 tw = __ldg(&g_tw512[f]);                // e^{-2pi i f/512}
        float Sx = Ex + Ox * tw.x - Oy * tw.y;
        float Sy = Ey + Ox * tw.y + Oy * tw.x;
        Pout[f] = Sx * Sx + Sy * Sy;
    }
    if (g == 0) {
        float v = X[0].x - X[0].y;                     // Nyquist: E[0] - O[0]
        Pout[256] = v * v;
    }
}

// ---------------------------------------------------------------------------
// K5: per-pair EDR + loss partials (deterministic block reduction).
// 10*log10(x) = (10/log2(10)) * log2(x), via MUFU __log2f.
// ---------------------------------------------------------------------------
__global__ void __launch_bounds__(512) k_loss() {
    __shared__ float sn[512], sd[512];
    int tid = threadIdx.x;
    int s   = blockIdx.x;                       // 0..127
    const float K = 3.0102999566398120f;        // 10 / log2(10)
    float num = 0.f, den = 0.f;
    if (tid < FBINS) {
        const float* pt = g_P + (size_t)s * TFRAMES * FBINS + tid;
        const float* pa = g_P + (size_t)(s + 128) * TFRAMES * FBINS + tid;
        float st = 0.f, sv = 0.f;
        for (int t = TFRAMES - 1; t >= 0; --t) {
            st += pt[t * FBINS];
            sv += pa[t * FBINS];
            float et = K * __log2f(st);
            float ea = K * __log2f(sv);
            num += fabsf(et - ea);
            den += fabsf(et);
        }
    }
    sn[tid] = num; sd[tid] = den;
    __syncthreads();
    for (int off = 256; off > 0; off >>= 1) {
        if (tid < off) { sn[tid] += sn[tid + off]; sd[tid] += sd[tid + off]; }
        __syncthreads();
    }
    if (tid == 0) {
        g_partial[2 * s]     = sn[0];
        g_partial[2 * s + 1] = sd[0];
    }
}

__global__ void k_final(float* __restrict__ out) {
    double n = 0.0, d = 0.0;
    for (int i = 0; i < 128; i++) {
        n += (double)g_partial[2 * i];
        d += (double)g_partial[2 * i + 1];
    }
    out[0] = (float)(n / d);
}

// ---------------------------------------------------------------------------
extern "C" void kernel_launch(void* const* d_in, const int* in_sizes, int n_in,
                              void* d_out, int out_size) {
    const float* tre = (const float*)d_in[0];
    const float* tim = (const float*)d_in[1];
    const float* are = (const float*)d_in[2];
    const float* aim = (const float*)d_in[3];

    k_setup <<<94, 512>>>();
    k_pack  <<<dim3(375, NSIG), 128>>>(tre, tim, are, aim);
    k_stage1<<<dim3(8,   NSIG), 125>>>();
    k_stage2<<<dim3(48,  NSIG), 128>>>();
    k_stft  <<<dim3(187, NSIG), 128>>>();
    k_loss  <<<128, 512>>>();
    k_final <<<1, 1>>>((float*)d_out);
}

// round 10
// speedup vs baseline: 3.0409x; 1.1806x over previous
#include <cuda_runtime.h>
#include <math.h>

// ---------------------------------------------------------------------------
// EDR loss pipeline (round 7):
//   pack fused into IFFT stage1 -> complex IFFT(48000) = 48 (=8x6 regs) x 1000 (=10^3 smem)
//   -> Hann STFT via 2-pass radix-16 FFT-256 (8 frames/CTA, 2 barriers)
//   -> power -> suffix-sum over frames -> 10*log10 -> sum|dt-da| / sum|dt|
// ---------------------------------------------------------------------------

#define NSIG     256
#define NHALF    48000
#define ROWLEN   96000
#define TFRAMES  374
#define FBINS    257

// scratch (allowed: __device__ globals)
__device__ float2 g_bufA[NSIG * NHALF];              // y (time domain packed)
__device__ float2 g_bufB[NSIG * NHALF];              // stage-1 intermediate
__device__ float  g_P[NSIG * TFRAMES * FBINS];
__device__ float  g_partial[256];

// twiddle tables
__device__ float2 g_twpack[48000];    // e^{+2pi i k/96000}
__device__ float2 g_tw1000[1000];     // e^{+2pi i t/1000}
__device__ float2 g_tw48[48];         // e^{+2pi i t/48}
__device__ float2 g_tw10[10];         // e^{+2pi i t/10}
__device__ float2 g_tw256f[256];      // e^{-2pi i t/256}
__device__ float2 g_tw512[256];       // e^{-2pi i f/512}
__device__ float2 g_hann2[256];       // (hann(2i), hann(2i+1)), periodic Hann 512

__device__ __forceinline__ void cmac(float2& acc, float2 a, float2 w) {
    acc.x += a.x * w.x - a.y * w.y;
    acc.y += a.x * w.y + a.y * w.x;
}
__device__ __forceinline__ float2 cadd(float2 a, float2 b){ return make_float2(a.x+b.x, a.y+b.y); }
__device__ __forceinline__ float2 csub(float2 a, float2 b){ return make_float2(a.x-b.x, a.y-b.y); }
__device__ __forceinline__ float2 cmul(float2 a, float2 b){
    return make_float2(a.x*b.x - a.y*b.y, a.x*b.y + a.y*b.x);
}
__device__ __forceinline__ float2 cmuli(float2 a){ return make_float2(-a.y, a.x); }   // +i*a
__device__ __forceinline__ float2 cmulni(float2 a){ return make_float2(a.y, -a.x); }  // -i*a

// ---------------------------------------------------------------------------
__global__ void __launch_bounds__(512) k_setup() {
    int t = blockIdx.x * 512 + threadIdx.x;
    float s, c;
    if (t < 48000) {
        sincosf((float)t * 6.5449846949787352e-5f, &s, &c);   // +2pi/96000
        g_twpack[t] = make_float2(c, s);
    }
    if (t < 1000) {
        sincosf((float)t * 6.2831853071795865e-3f, &s, &c);   // +2pi/1000
        g_tw1000[t] = make_float2(c, s);
    }
    if (t < 48) {
        sincosf((float)t * 0.13089969389957472f, &s, &c);     // +2pi/48
        g_tw48[t] = make_float2(c, s);
    }
    if (t < 10) {
        sincosf((float)t * 0.62831853071795865f, &s, &c);     // +2pi/10
        g_tw10[t] = make_float2(c, s);
    }
    if (t < 256) {
        sincosf(-(float)t * 2.4543692606170259e-2f, &s, &c);  // -2pi/256
        g_tw256f[t] = make_float2(c, s);
        sincosf(-(float)t * 1.2271846303085130e-2f, &s, &c);  // -2pi/512
        g_tw512[t] = make_float2(c, s);
        float w0 = 0.5f - 0.5f * cosf((float)(2 * t)     * 1.2271846303085130e-2f);
        float w1 = 0.5f - 0.5f * cosf((float)(2 * t + 1) * 1.2271846303085130e-2f);
        g_hann2[t] = make_float2(w0, w1);
    }
}

// ---------------------------------------------------------------------------
// K2: fused pack + stage 1 of IFFT-48000.
// Per thread (k2 in 0..999): for each k1<48, k = k2 + 1000*k1:
//   pack  Y[k] = E + i*O from the 4 input arrays (inline, coalesced reads)
//   then 48-point DFT over k1 (8x6 CT in registers),
//   final twiddle e^{+2pi i k2 m/48000}/48000 by complex recurrence.
// ---------------------------------------------------------------------------
__global__ void __launch_bounds__(125) k_stage1(const float* __restrict__ tre,
                                                const float* __restrict__ tim,
                                                const float* __restrict__ are,
                                                const float* __restrict__ aim) {
    __shared__ float2 sW[48];
    int tid = threadIdx.x;               // 0..124
    int sig = blockIdx.y;
    int k2  = blockIdx.x * 125 + tid;    // 8 blocks * 125 = 1000

    if (tid < 48) sW[tid] = g_tw48[tid];
    __syncthreads();

    const float* re = (sig < 128 ? tre : are) + (size_t)(sig & 127) * ROWLEN;
    const float* im = (sig < 128 ? tim : aim) + (size_t)(sig & 127) * ROWLEN;

    float2 v[48];
#pragma unroll
    for (int k1 = 0; k1 < 48; k1++) {
        int k = k2 + 1000 * k1;
        float ar = __ldg(&re[k]),          ai = __ldg(&im[k]);
        float br = __ldg(&re[NHALF - k]),  bi = -__ldg(&im[NHALF - k]);
        float Ex = 0.5f * (ar + br), Ey = 0.5f * (ai + bi);
        float Dx = 0.5f * (ar - br), Dy = 0.5f * (ai - bi);
        float2 w = __ldg(&g_twpack[k]);                      // e^{+2pi i k/96000}
        float Ox = w.x * Dx - w.y * Dy;
        float Oy = w.x * Dy + w.y * Dx;
        v[k1] = make_float2(Ex - Oy, Ey + Ox);
    }
    if (k2 == 0) {                        // k==0 special case (k1=0 only)
        float r0 = __ldg(&re[0]), rM = __ldg(&re[NHALF]);
        v[0] = make_float2(0.5f * (r0 + rM), 0.5f * (r0 - rM));
    }

    // six DFT-8s (positive exponent), in place: v[6r+b] = F_b[r]
    const float C = 0.70710678118654752f;
#pragma unroll
    for (int b = 0; b < 6; b++) {
        float2 x0 = v[b],      x1 = v[b + 6],  x2 = v[b + 12], x3 = v[b + 18];
        float2 x4 = v[b + 24], x5 = v[b + 30], x6 = v[b + 36], x7 = v[b + 42];
        float2 g0 = cadd(x0, x4), g1 = csub(x0, x4);
        float2 g2 = cadd(x2, x6), g3 = csub(x2, x6);
        float2 h0 = cadd(x1, x5), h1 = csub(x1, x5);
        float2 h2 = cadd(x3, x7), h3 = csub(x3, x7);
        float2 ig3 = cmuli(g3), ih3 = cmuli(h3);
        float2 E0 = cadd(g0, g2), E2 = csub(g0, g2);
        float2 E1 = cadd(g1, ig3), E3 = csub(g1, ig3);
        float2 O0 = cadd(h0, h2), O2 = csub(h0, h2);
        float2 O1 = cadd(h1, ih3), O3 = csub(h1, ih3);
        float2 W1O1 = make_float2(C * (O1.x - O1.y),  C * (O1.x + O1.y));   // e^{+i pi/4}  * O1
        float2 W3O3 = make_float2(-C * (O3.x + O3.y), C * (O3.x - O3.y));   // e^{+i 3pi/4} * O3
        float2 iO2  = cmuli(O2);
        v[b]      = cadd(E0, O0);
        v[b + 6]  = cadd(E1, W1O1);
        v[b + 12] = cadd(E2, iO2);
        v[b + 18] = cadd(E3, W3O3);
        v[b + 24] = csub(E0, O0);
        v[b + 30] = csub(E1, W1O1);
        v[b + 36] = csub(E2, iO2);
        v[b + 42] = csub(E3, W3O3);
    }

    // per-thread twiddle recurrence: w_m = (1/48000) * e^{+2pi i k2 m/48000}
    float sn, cs;
    sincosf((float)k2 * 1.3089969389957471e-4f, &sn, &cs);
    float2 wstep = make_float2(cs, sn);
    float2 w = make_float2(1.0f / 48000.0f, 0.0f);

    float2* dstBase = g_bufB + (size_t)sig * NHALF;
#pragma unroll
    for (int m = 0; m < 48; m++) {
        int r6 = 6 * (m & 7);
        float2 acc = v[r6];
#pragma unroll
        for (int b = 1; b < 6; b++)
            cmac(acc, v[r6 + b], sW[(b * m) % 48]);
        dstBase[m * 1000 + k2] = cmul(acc, w);
        w = cmul(w, wstep);
    }
}

// ---------------------------------------------------------------------------
// K3: stage 2 — 1000-point inverse DFT per (sig,m1) row, 3-pass radix-10
// Stockham (sign +). Coalesced smem staging of input, then streaming
// accumulation: x read one at a time, acc[10] register outputs; twiddles by
// complex recurrence. ~56 live regs (vs 80 with in[10]+acc[10]).
// ---------------------------------------------------------------------------
__global__ void __launch_bounds__(128) k_stage2() {
    __shared__ float2 sA[1000];
    __shared__ float2 sB[1000];
    __shared__ float2 sW10[10];
    int tid = threadIdx.x;
    int m1  = blockIdx.x;   // 0..47
    int sig = blockIdx.y;   // 0..255

    if (tid < 10) sW10[tid] = g_tw10[tid];

    const float2* src = g_bufB + ((size_t)sig * 48 + m1) * 1000;
    for (int i = tid; i < 1000; i += 128) sA[i] = __ldg(&src[i]);   // coalesced stage

    bool act = (tid < 100);
    int g = tid;
    int p1 = g / 10;
    float2 wg = make_float2(1.f, 0.f), wp = make_float2(1.f, 0.f);
    if (act) {
        wg = __ldg(&g_tw1000[g]);          // e^{+2pi i g/1000}
        wp = __ldg(&g_tw1000[10 * p1]);    // e^{+2pi i p1/100}
    }
    __syncthreads();

    float2 acc[10];

    // ---- pass 0: nn=1000, p=g: out[10g+j] = wg^j * sum_r sA[g+100r] w10^{rj}
    if (act) {
        float2 x = sA[g];
#pragma unroll
        for (int j = 0; j < 10; j++) acc[j] = x;
#pragma unroll
        for (int r = 1; r < 10; r++) {
            x = sA[g + 100 * r];
#pragma unroll
            for (int j = 0; j < 10; j++) cmac(acc[j], x, sW10[(r * j) % 10]);
        }
        float2 w = make_float2(1.f, 0.f);
        sB[10 * g] = acc[0];
#pragma unroll
        for (int j = 1; j < 10; j++) {
            w = cmul(w, wg);
            sB[10 * g + j] = cmul(acc[j], w);
        }
    }
    __syncthreads();

    // ---- pass 1: nn=100, p=p1: out[g + 90 p1 + 10j], tw = wp^j
    if (act) {
        float2 x = sB[g];
#pragma unroll
        for (int j = 0; j < 10; j++) acc[j] = x;
#pragma unroll
        for (int r = 1; r < 10; r++) {
            x = sB[g + 100 * r];
#pragma unroll
            for (int j = 0; j < 10; j++) cmac(acc[j], x, sW10[(r * j) % 10]);
        }
        int ob = g + 90 * p1;
        float2 w = make_float2(1.f, 0.f);
        sA[ob] = acc[0];
#pragma unroll
        for (int j = 1; j < 10; j++) {
            w = cmul(w, wp);
            sA[ob + 10 * j] = cmul(acc[j], w);
        }
    }
    __syncthreads();

    // ---- pass 2: nn=10, p=0: out[g + 100j], no twiddle; straight to gmem
    if (act) {
        float2 x = sA[g];
#pragma unroll
        for (int j = 0; j < 10; j++) acc[j] = x;
#pragma unroll
        for (int r = 1; r < 10; r++) {
            x = sA[g + 100 * r];
#pragma unroll
            for (int j = 0; j < 10; j++) cmac(acc[j], x, sW10[(r * j) % 10]);
        }
        float2* dst = g_bufA + (size_t)sig * NHALF + m1;   // y[m1 + 48*m2]
#pragma unroll
        for (int j = 0; j < 10; j++) dst[48 * (g + 100 * j)] = acc[j];
    }
}

// ---------------------------------------------------------------------------
// Register DFT-16 (forward, sign -): out[j] = sum_m v[m] e^{-2pi i m j /16},
// natural order in/out, via 4x4 Cooley-Tukey with constant twiddles.
// ---------------------------------------------------------------------------
__device__ __forceinline__ void dft16(float2* v) {
    const float C1 = 0.92387953251128675613f;   // cos(pi/8)
    const float S1 = 0.38268343236508977173f;   // sin(pi/8)
    const float R  = 0.70710678118654752440f;   // sqrt(2)/2
    float2 T[16];
#pragma unroll
    for (int m1 = 0; m1 < 4; m1++) {
        float2 a = v[m1], b = v[m1 + 4], c = v[m1 + 8], d = v[m1 + 12];
        float2 s0 = cadd(a, c), s1 = csub(a, c);
        float2 s2 = cadd(b, d), s3 = csub(b, d);
        T[4 * m1 + 0] = cadd(s0, s2);
        T[4 * m1 + 1] = cadd(s1, cmulni(s3));   // s1 - i*s3
        T[4 * m1 + 2] = csub(s0, s2);
        T[4 * m1 + 3] = csub(s1, cmulni(s3));   // s1 + i*s3
    }
    // twiddles W16^{-m1*j2}
    T[5]  = cmul(T[5],  make_float2( C1, -S1));   // W^-1
    T[6]  = cmul(T[6],  make_float2(  R,  -R));   // W^-2
    T[7]  = cmul(T[7],  make_float2( S1, -C1));   // W^-3
    T[9]  = cmul(T[9],  make_float2(  R,  -R));   // W^-2
    T[10] = cmulni(T[10]);                        // W^-4 = -i
    T[11] = cmul(T[11], make_float2( -R,  -R));   // W^-6
    T[13] = cmul(T[13], make_float2( S1, -C1));   // W^-3
    T[14] = cmul(T[14], make_float2( -R,  -R));   // W^-6
    T[15] = cmul(T[15], make_float2(-C1,  S1));   // W^-9
#pragma unroll
    for (int j2 = 0; j2 < 4; j2++) {
        float2 a = T[j2], b = T[4 + j2], c = T[8 + j2], d = T[12 + j2];
        float2 s0 = cadd(a, c), s1 = csub(a, c);
        float2 s2 = cadd(b, d), s3 = csub(b, d);
        v[j2]      = cadd(s0, s2);
        v[4 + j2]  = cadd(s1, cmulni(s3));
        v[8 + j2]  = csub(s0, s2);
        v[12 + j2] = csub(s1, cmulni(s3));
    }
}

// ---------------------------------------------------------------------------
// K4: STFT frame power via 2-pass radix-16 FFT-256 (sign -).
// 16 threads per frame, 8 frames per 128-thread CTA, 2 barriers.
// n = n1 + 16 n2, k = 16 k1 + k2:
//   pass0 (thread n1): A[k2] = sum_{n2} z[n1+16n2] W16^{-n2 k2};
//                      B[n1][k2] = A[k2] * W256^{-n1 k2}   (recurrence)
//   pass1 (thread k2): X[16k1+k2] = sum_{n1} B[n1][k2] W16^{-n1 k1}
// then rfft unpack -> |.|^2 into g_P.
// ---------------------------------------------------------------------------
__global__ void __launch_bounds__(128) k_stft() {
    __shared__ float2 sMid[8][272];   // [n1*17 + k2], padded
    __shared__ float2 sOut[8][256];   // X natural order
    int tid = threadIdx.x;
    int lf  = tid >> 4;               // local frame 0..7
    int i   = tid & 15;               // n1 (pass0) / k2 (pass1)
    int fr  = blockIdx.x * 8 + lf;
    int sig = blockIdx.y;
    bool ok = fr < TFRAMES;

    float2 v[16];
    if (ok) {
        const float2* src = g_bufA + (size_t)sig * NHALF + 128 * fr;
#pragma unroll
        for (int n2 = 0; n2 < 16; n2++) {
            int idx = i + 16 * n2;
            float2 y = __ldg(&src[idx]);
            float2 h = __ldg(&g_hann2[idx]);
            v[n2] = make_float2(y.x * h.x, y.y * h.y);
        }
        dft16(v);                                   // v[k2] = A[k2]
        float2 wb = __ldg(&g_tw256f[i]);            // e^{-2pi i n1/256}
        float2 w = make_float2(1.f, 0.f);
        sMid[lf][i * 17] = v[0];
#pragma unroll
        for (int k2 = 1; k2 < 16; k2++) {
            w = cmul(w, wb);
            sMid[lf][i * 17 + k2] = cmul(v[k2], w);
        }
    }
    __syncthreads();

    if (ok) {
#pragma unroll
        for (int n1 = 0; n1 < 16; n1++) v[n1] = sMid[lf][n1 * 17 + i];
        dft16(v);                                   // v[k1] = X[16k1 + i]
#pragma unroll
        for (int k1 = 0; k1 < 16; k1++) sOut[lf][16 * k1 + i] = v[k1];
    }
    __syncthreads();

    if (ok) {
        float* Pout = g_P + ((size_t)sig * TFRAMES + fr) * FBINS;
#pragma unroll
        for (int h = 0; h < 16; h++) {
            int f = i + 16 * h;
            float2 z1 = sOut[lf][f];
            float2 z2 = sOut[lf][(256 - f) & 255]; z2.y = -z2.y;
            float Ex = 0.5f * (z1.x + z2.x), Ey = 0.5f * (z1.y + z2.y);
            float Dx = 0.5f * (z1.x - z2.x), Dy = 0.5f * (z1.y - z2.y);
            float Ox = Dy, Oy = -Dx;                     // O = D / i
            float2 tw = __ldg(&g_tw512[f]);              // e^{-2pi i f/512}
            float Sx = Ex + Ox * tw.x - Oy * tw.y;
            float Sy = Ey + Ox * tw.y + Oy * tw.x;
            Pout[f] = Sx * Sx + Sy * Sy;
        }
        if (i == 0) {
            float nv = sOut[lf][0].x - sOut[lf][0].y;    // Nyquist: E[0]-O[0]
            Pout[256] = nv * nv;
        }
    }
}

// ---------------------------------------------------------------------------
// K5: per-pair EDR + loss partials (deterministic block reduction).
// ---------------------------------------------------------------------------
__global__ void __launch_bounds__(512) k_loss() {
    __shared__ float sn[512], sd[512];
    int tid = threadIdx.x;
    int s   = blockIdx.x;                       // 0..127
    const float K = 3.0102999566398120f;        // 10 / log2(10)
    float num = 0.f, den = 0.f;
    if (tid < FBINS) {
        const float* pt = g_P + (size_t)s * TFRAMES * FBINS + tid;
        const float* pa = g_P + (size_t)(s + 128) * TFRAMES * FBINS + tid;
        float st = 0.f, sv = 0.f;
        for (int t = TFRAMES - 1; t >= 0; --t) {
            st += pt[t * FBINS];
            sv += pa[t * FBINS];
            float et = K * __log2f(st);
            float ea = K * __log2f(sv);
            num += fabsf(et - ea);
            den += fabsf(et);
        }
    }
    sn[tid] = num; sd[tid] = den;
    __syncthreads();
    for (int off = 256; off > 0; off >>= 1) {
        if (tid < off) { sn[tid] += sn[tid + off]; sd[tid] += sd[tid + off]; }
        __syncthreads();
    }
    if (tid == 0) {
        g_partial[2 * s]     = sn[0];
        g_partial[2 * s + 1] = sd[0];
    }
}

__global__ void k_final(float* __restrict__ out) {
    double n = 0.0, d = 0.0;
    for (int i = 0; i < 128; i++) {
        n += (double)g_partial[2 * i];
        d += (double)g_partial[2 * i + 1];
    }
    out[0] = (float)(n / d);
}

// ---------------------------------------------------------------------------
extern "C" void kernel_launch(void* const* d_in, const int* in_sizes, int n_in,
                              void* d_out, int out_size) {
    const float* tre = (const float*)d_in[0];
    const float* tim = (const float*)d_in[1];
    const float* are = (const float*)d_in[2];
    const float* aim = (const float*)d_in[3];

    k_setup <<<94, 512>>>();
    k_stage1<<<dim3(8,  NSIG), 125>>>(tre, tim, are, aim);
    k_stage2<<<dim3(48, NSIG), 128>>>();
    k_stft  <<<dim3(47, NSIG), 128>>>();
    k_loss  <<<128, 512>>>();
    k_final <<<1, 1>>>((float*)d_out);
}